// round 12
// baseline (speedup 1.0000x reference)
#include <cuda_runtime.h>
#include <math.h>

#define B_    4
#define N_    8192
#define F_    64
#define NIN_  67
#define NBLK  148
#define TPB   384
#define PPB   224            // points per block (112 lane-pairs x 2 points = 7 full warps)
#define MLPT  224            // MLP threads per block = warps 0..6 exactly
#define NPTS  (B_ * N_)

#define S_OFF 0
#define F_OFF (B_ * N_)
#define C_OFF (B_ * N_ + B_ * N_ * F_)

// ---------------- scratch (no allocations allowed) ----------------
__device__ float             g_comp[B_][N_][3];  // compacted selected points
__device__ unsigned          g_arrive = 0;       // grid-barrier arrival counter
__device__ volatile unsigned g_gen    = 0;       // grid-barrier generation

// ---------------- f32x2 helpers (sm_103a packed fp32) ----------------
static __device__ __forceinline__ unsigned long long pack2(float lo, float hi) {
    unsigned long long r;
    asm("mov.b64 %0, {%1, %2};" : "=l"(r) : "f"(lo), "f"(hi));
    return r;
}
static __device__ __forceinline__ void unpack2(unsigned long long v, float& lo, float& hi) {
    asm("mov.b64 {%0, %1}, %2;" : "=f"(lo), "=f"(hi) : "l"(v));
}
static __device__ __forceinline__ unsigned long long ffma2(
    unsigned long long a, unsigned long long b, unsigned long long c) {
    unsigned long long d;
    asm("fma.rn.f32x2 %0, %1, %2, %3;" : "=l"(d) : "l"(a), "l"(b), "l"(c));
    return d;
}

static __device__ __forceinline__ bool read_mask(const void* m, int idx, int mode) {
    if (mode == 1) return ((const int*)m)[idx] != 0;
    if (mode == 2) return ((const float*)m)[idx] != 0.0f;
    return ((const unsigned char*)m)[idx] != 0;
}

// Replay-safe grid-wide barrier (grid == 148 == SM count, 1 block/SM).
static __device__ __forceinline__ void grid_barrier() {
    __syncthreads();
    if (threadIdx.x == 0) {
        unsigned gen = g_gen;
        __threadfence();
        if (atomicAdd(&g_arrive, 1u) == NBLK - 1u) {
            atomicExch(&g_arrive, 0u);
            __threadfence();
            g_gen = gen + 1u;
        } else {
            while (g_gen == gen) __nanosleep(40);
        }
        __threadfence();
    }
    __syncthreads();
}

// ---------------- the single fused kernel ----------------
__global__ void __launch_bounds__(TPB, 1)
fused_kernel(const float* __restrict__ points, const float* __restrict__ features,
             const void* __restrict__ mask,
             const float* __restrict__ W1, const float* __restrict__ b1,
             const float* __restrict__ W2, const float* __restrict__ b2,
             const float* __restrict__ W3, const float* __restrict__ b3,
             float* __restrict__ out) {
    // weights staged as f32x2 neuron pairs, 4 neurons per ulonglong2 (LDS.128)
    __shared__ ulonglong2         sW1[NIN_ * 16];  // [j][p]: neurons 4p..4p+3
    __shared__ unsigned long long sB1[32];
    __shared__ ulonglong2         sW2[64 * 8];     // [j][q]: neurons 4q..4q+3
    __shared__ unsigned long long sB2[16];
    __shared__ float              sW3[32];
    __shared__ float              sB3v;
    __shared__ int                s_fl[2];
    // finalize scratch (12 warps)
    __shared__ double sred[12], sred2[12];
    __shared__ int    wsum[12], woff[12];
    __shared__ int    s_nleaf, s_cnt;
    __shared__ double bSs, bSs2;

    const int tid  = threadIdx.x;
    const int bid  = blockIdx.x;
    const int lane = tid & 31, wid = tid >> 5;

    // ---- inline mask dtype detection (first 64 words; 0/1 data disambiguates) ----
    if (tid < 2) s_fl[tid] = 0;
    __syncthreads();
    {
        unsigned v = ((const unsigned*)mask)[tid & 63];
        if (v > 1u) atomicOr(&s_fl[0], 1);
        if (v != 0u && v != 0x3F800000u) atomicOr(&s_fl[1], 1);
    }

    // ---- weight staging ----
    for (int idx = tid; idx < NIN_ * 16; idx += TPB) {
        int j = idx >> 4, p = idx & 15;
        ulonglong2 w;
        w.x = pack2(W1[(4 * p + 0) * NIN_ + j], W1[(4 * p + 1) * NIN_ + j]);
        w.y = pack2(W1[(4 * p + 2) * NIN_ + j], W1[(4 * p + 3) * NIN_ + j]);
        sW1[idx] = w;
    }
    for (int idx = tid; idx < 64 * 8; idx += TPB) {
        int j = idx >> 3, p = idx & 7;
        ulonglong2 w;
        w.x = pack2(W2[(4 * p + 0) * 64 + j], W2[(4 * p + 1) * 64 + j]);
        w.y = pack2(W2[(4 * p + 2) * 64 + j], W2[(4 * p + 3) * 64 + j]);
        sW2[idx] = w;
    }
    if (tid < 32) sB1[tid] = pack2(b1[2 * tid], b1[2 * tid + 1]);
    if (tid < 16) sB2[tid] = pack2(b2[2 * tid], b2[2 * tid + 1]);
    if (tid < 32) sW3[tid] = W3[tid];
    if (tid == 0) sB3v = b3[0];

    // ---- feature passthrough: flat coalesced grid-stride copy (all threads) ----
    {
        const float4* src = (const float4*)features;
        float4*       dst = (float4*)(out + F_OFF);
        const int total4 = (B_ * N_ * F_) / 4;  // 524288
        for (int i = bid * TPB + tid; i < total4; i += NBLK * TPB)
            dst[i] = src[i];
    }
    __syncthreads();
    const int mode = (!s_fl[0]) ? 1 : ((!s_fl[1]) ? 2 : 0);

    // ======== MLP: 2 POINTS per thread, lane-pair neuron split ========
    // even lane of pair: layer-1 neurons 0..31, layer-2 neurons 0..15 (both points)
    // odd  lane of pair: layer-1 neurons 32..63, layer-2 neurons 16..31 (both points)
    // Each weight LDS.128 now feeds 4 FFMA2 (2 neurons-pairs x 2 points).
    // Region = threads 0..223 = warps 0..6 EXACTLY (full warps for sync ops).
    if (tid < MLPT) {
        const int  base   = bid * PPB + 2 * (tid >> 1);
        const bool validA = (base     < NPTS);
        const bool validB = (base + 1 < NPTS);
        const int  ptA    = validA ? base     : (NPTS - 1);
        const int  ptB    = validB ? base + 1 : (NPTS - 1);
        const int  oddt   = tid & 1;
        const bool mA     = read_mask(mask, ptA, mode);
        const bool mB     = read_mask(mask, ptB, mode);

        float scoreA = 0.0f, scoreB = 0.0f;
        if (__any_sync(0xFFFFFFFFu, (mA && validA) || (mB && validB))) {
            const float4* fvA = (const float4*)(features + (size_t)ptA * F_);
            const float4* fvB = (const float4*)(features + (size_t)ptB * F_);
            const int hb = oddt ? 8 : 0;        // ulonglong2 offset into sW1 row
            const int qb = oddt ? 4 : 0;        // ulonglong2 offset into sW2 row

            unsigned long long accA[16], accB[16];
#pragma unroll
            for (int p = 0; p < 16; p++) { accA[p] = sB1[oddt * 16 + p]; accB[p] = accA[p]; }

#pragma unroll 4
            for (int c = 0; c < 16; c++) {
                float4 vA = fvA[c];
                float4 vB = fvB[c];
                float xsA[4] = {vA.x, vA.y, vA.z, vA.w};
                float xsB[4] = {vB.x, vB.y, vB.z, vB.w};
#pragma unroll
                for (int u = 0; u < 4; u++) {
                    unsigned long long xA = pack2(xsA[u], xsA[u]);
                    unsigned long long xB = pack2(xsB[u], xsB[u]);
                    const ulonglong2* wrow = &sW1[(4 * c + u) * 16 + hb];
#pragma unroll
                    for (int p = 0; p < 8; p++) {
                        ulonglong2 w = wrow[p];
                        accA[2 * p]     = ffma2(xA, w.x, accA[2 * p]);
                        accA[2 * p + 1] = ffma2(xA, w.y, accA[2 * p + 1]);
                        accB[2 * p]     = ffma2(xB, w.x, accB[2 * p]);
                        accB[2 * p + 1] = ffma2(xB, w.y, accB[2 * p + 1]);
                    }
                }
            }
            {   // xyz tail (inputs 64..66)
                const float* ppA = points + (size_t)ptA * 3;
                const float* ppB = points + (size_t)ptB * 3;
#pragma unroll
                for (int u = 0; u < 3; u++) {
                    unsigned long long xA = pack2(ppA[u], ppA[u]);
                    unsigned long long xB = pack2(ppB[u], ppB[u]);
                    const ulonglong2* wrow = &sW1[(64 + u) * 16 + hb];
#pragma unroll
                    for (int p = 0; p < 8; p++) {
                        ulonglong2 w = wrow[p];
                        accA[2 * p]     = ffma2(xA, w.x, accA[2 * p]);
                        accA[2 * p + 1] = ffma2(xA, w.y, accA[2 * p + 1]);
                        accB[2 * p]     = ffma2(xB, w.x, accB[2 * p]);
                        accB[2 * p + 1] = ffma2(xB, w.y, accB[2 * p + 1]);
                    }
                }
            }

            // relu -> this thread's 32 h1 values per point
            float h1A[32], h1B[32];
#pragma unroll
            for (int p = 0; p < 16; p++) {
                float lo, hi;
                unpack2(accA[p], lo, hi);
                h1A[2 * p] = fmaxf(lo, 0.0f); h1A[2 * p + 1] = fmaxf(hi, 0.0f);
                unpack2(accB[p], lo, hi);
                h1B[2 * p] = fmaxf(lo, 0.0f); h1B[2 * p + 1] = fmaxf(hi, 0.0f);
            }

            // layer 2: h1[j] broadcast within the lane pair, feeds both points
            unsigned long long acc2A[8], acc2B[8];
#pragma unroll
            for (int q = 0; q < 8; q++) { acc2A[q] = sB2[oddt * 8 + q]; acc2B[q] = acc2A[q]; }
#pragma unroll 8
            for (int j = 0; j < 64; j++) {
                float hvA = __shfl_sync(0xFFFFFFFFu, h1A[j & 31], j >> 5, 2);
                float hvB = __shfl_sync(0xFFFFFFFFu, h1B[j & 31], j >> 5, 2);
                unsigned long long hA = pack2(hvA, hvA);
                unsigned long long hB = pack2(hvB, hvB);
                const ulonglong2* wrow = &sW2[j * 8 + qb];
#pragma unroll
                for (int q = 0; q < 4; q++) {
                    ulonglong2 w = wrow[q];
                    acc2A[2 * q]     = ffma2(hA, w.x, acc2A[2 * q]);
                    acc2A[2 * q + 1] = ffma2(hA, w.y, acc2A[2 * q + 1]);
                    acc2B[2 * q]     = ffma2(hB, w.x, acc2B[2 * q]);
                    acc2B[2 * q + 1] = ffma2(hB, w.y, acc2B[2 * q + 1]);
                }
            }

            // layer 3 partials over this thread's 16 layer-2 neurons
            float zA = 0.0f, zB = 0.0f;
#pragma unroll
            for (int q = 0; q < 8; q++) {
                float lo, hi;
                int n = oddt * 16 + 2 * q;
                unpack2(acc2A[q], lo, hi);
                zA += fmaxf(lo, 0.0f) * sW3[n] + fmaxf(hi, 0.0f) * sW3[n + 1];
                unpack2(acc2B[q], lo, hi);
                zB += fmaxf(lo, 0.0f) * sW3[n] + fmaxf(hi, 0.0f) * sW3[n + 1];
            }
            zA += __shfl_xor_sync(0xFFFFFFFFu, zA, 1);
            zB += __shfl_xor_sync(0xFFFFFFFFu, zB, 1);
            zA += sB3v; zB += sB3v;
            scoreA = 1.0f / (1.0f + expf(-zA));
            scoreB = 1.0f / (1.0f + expf(-zB));
        }
        // even lane writes point A, odd lane writes point B (balanced)
        if (!oddt) { if (validA) out[S_OFF + ptA] = mA ? scoreA : 0.0f; }
        else       { if (validB) out[S_OFF + ptB] = mB ? scoreB : 0.0f; }
    }

    // ================= grid-wide barrier =================
    grid_barrier();

    if (bid >= B_) return;

    // ================= finalize: batch b = bid, 384 threads =================
    const int    b      = bid;
    float*       scores = out + S_OFF + b * N_;
    const float* pts    = points + (size_t)b * N_ * 3;

    // balanced contiguous partition of N_ over TPB threads (order-preserving)
    const int q_   = N_ / TPB;               // 21
    const int r_   = N_ % TPB;               // 128
    const int len  = q_ + (tid < r_ ? 1 : 0);      // 21 or 22
    const int st   = tid * q_ + (tid < r_ ? tid : r_);

    // ---- n_leaf ----
    {
        int lc = 0;
#pragma unroll 22
        for (int k = 0; k < 22; k++)
            if (k < len) lc += read_mask(mask, b * N_ + st + k, mode) ? 1 : 0;
#pragma unroll
        for (int o = 16; o > 0; o >>= 1) lc += __shfl_down_sync(0xFFFFFFFFu, lc, o);
        if (lane == 0) wsum[wid] = lc;
        __syncthreads();
        if (tid == 0) {
            int s = 0;
#pragma unroll
            for (int w = 0; w < 12; w++) s += wsum[w];
            s_nleaf = s;
        }
        __syncthreads();
    }
    const int n_leaf = s_nleaf;
    __syncthreads();

    // ---- load scores, apply n_leaf<10 zeroing, sums ----
    float sv[22];
    const float zfac = (n_leaf < 10) ? 0.0f : 1.0f;
    double ls = 0.0, ls2 = 0.0;
#pragma unroll 22
    for (int k = 0; k < 22; k++) {
        float s = 0.0f;
        if (k < len) s = scores[st + k] * zfac;
        sv[k] = s;
        ls += s; ls2 += (double)s * (double)s;
    }
    if (n_leaf < 10) {
#pragma unroll 22
        for (int k = 0; k < 22; k++)
            if (k < len) scores[st + k] = 0.0f;
    }
#pragma unroll
    for (int o = 16; o > 0; o >>= 1) {
        ls  += __shfl_down_sync(0xFFFFFFFFu, ls, o);
        ls2 += __shfl_down_sync(0xFFFFFFFFu, ls2, o);
    }
    if (lane == 0) { sred[wid] = ls; sred2[wid] = ls2; }
    __syncthreads();
    if (tid == 0) {
        double a = 0.0, c = 0.0;
#pragma unroll
        for (int w = 0; w < 12; w++) { a += sred[w]; c += sred2[w]; }
        bSs = a; bSs2 = c;
    }
    __syncthreads();

    // ---- selection (> 0.7), stable compaction by index ----
    int c = 0;
#pragma unroll 22
    for (int k = 0; k < 22; k++)
        if (k < len) c += (sv[k] > 0.7f) ? 1 : 0;
    int incl = c;
#pragma unroll
    for (int o = 1; o < 32; o <<= 1) {
        int t = __shfl_up_sync(0xFFFFFFFFu, incl, o);
        if (lane >= o) incl += t;
    }
    if (lane == 31) wsum[wid] = incl;
    __syncthreads();
    if (tid == 0) {
        int run = 0;
#pragma unroll
        for (int w = 0; w < 12; w++) { int t = wsum[w]; woff[w] = run; run += t; }
        s_cnt = run;
    }
    __syncthreads();
    int       pos = incl - c + woff[wid];
    const int cnt = s_cnt;
#pragma unroll 22
    for (int k = 0; k < 22; k++) {
        if (k < len && sv[k] > 0.7f) {
            int n = st + k;
            g_comp[b][pos][0] = pts[n * 3 + 0];
            g_comp[b][pos][1] = pts[n * 3 + 1];
            g_comp[b][pos][2] = pts[n * 3 + 2];
            pos++;
        }
    }
    __syncthreads();

    // ---- consecutive-distance variance among selected points ----
    double ld = 0.0, ld2 = 0.0;
    for (int k = tid; k < cnt - 1; k += TPB) {
        float dx = g_comp[b][k + 1][0] - g_comp[b][k][0];
        float dy = g_comp[b][k + 1][1] - g_comp[b][k][1];
        float dz = g_comp[b][k + 1][2] - g_comp[b][k][2];
        float dd = sqrtf(dx * dx + dy * dy + dz * dz);
        ld += dd; ld2 += (double)dd * (double)dd;
    }
#pragma unroll
    for (int o = 16; o > 0; o >>= 1) {
        ld  += __shfl_down_sync(0xFFFFFFFFu, ld, o);
        ld2 += __shfl_down_sync(0xFFFFFFFFu, ld2, o);
    }
    if (lane == 0) { sred[wid] = ld; sred2[wid] = ld2; }
    __syncthreads();
    if (tid == 0) {
        double Sd = 0.0, Sd2 = 0.0;
#pragma unroll
        for (int w = 0; w < 12; w++) { Sd += sred[w]; Sd2 += sred2[w]; }

        const double Ss = bSs, Ss2 = bSs2;
        double nl    = (double)n_leaf;
        double meanS = Ss / fmax(nl, 1.0);
        float  clarity = (float)((Ss2 - nl * meanS * meanS) / fmax(nl - 1.0, 1.0));
        int np = cnt - 1; if (np < 0) np = 0;
        double dnp   = (double)np;
        double meanD = Sd / fmax(dnp, 1.0);
        float  dvar  = (float)((Sd2 - dnp * meanD * meanD) / fmax(dnp - 1.0, 1.0));
        float cont = 1.0f / (dvar + 1e-8f);
        cont = fminf(fmaxf(cont, 0.0f), 1.0f);
        if (!(cnt > 5)) cont = 0.0f;
        float conf = fminf(fmaxf(clarity * cont, 0.0f), 1.0f);
        if (n_leaf == 0) conf = 0.0f;
        out[C_OFF + b] = conf;
    }
}

// ---------------- launch ----------------
extern "C" void kernel_launch(void* const* d_in, const int* in_sizes, int n_in,
                              void* d_out, int out_size) {
    const float* points   = (const float*)d_in[0];
    const float* features = (const float*)d_in[1];
    const void*  mask     = d_in[2];
    const float* W1 = (const float*)d_in[3];
    const float* b1 = (const float*)d_in[4];
    const float* W2 = (const float*)d_in[5];
    const float* b2 = (const float*)d_in[6];
    const float* W3 = (const float*)d_in[7];
    const float* b3 = (const float*)d_in[8];
    float* out = (float*)d_out;

    fused_kernel<<<NBLK, TPB>>>(points, features, mask,
                                W1, b1, W2, b2, W3, b3, out);
}

// round 13
// speedup vs baseline: 1.5548x; 1.5548x over previous
#include <cuda_runtime.h>
#include <math.h>

#define B_    4
#define N_    8192
#define F_    64
#define NIN_  67
#define NBLK  148
#define TPB   256
#define PPB   224            // points per block = 7 FULL warps; 148*224 = 33152 >= 32768
#define NPTS  (B_ * N_)

#define S_OFF 0
#define F_OFF (B_ * N_)
#define C_OFF (B_ * N_ + B_ * N_ * F_)

// ---------------- scratch (no allocations allowed) ----------------
__device__ int               g_nleaf[B_];      // n_leaf per batch (pre-barrier)
__device__ unsigned          g_arrive = 0;     // grid-barrier arrival counter
__device__ volatile unsigned g_gen    = 0;     // grid-barrier generation

// ---------------- f32x2 helpers (sm_103a packed fp32) ----------------
static __device__ __forceinline__ unsigned long long pack2(float lo, float hi) {
    unsigned long long r;
    asm("mov.b64 %0, {%1, %2};" : "=l"(r) : "f"(lo), "f"(hi));
    return r;
}
static __device__ __forceinline__ void unpack2(unsigned long long v, float& lo, float& hi) {
    asm("mov.b64 {%0, %1}, %2;" : "=f"(lo), "=f"(hi) : "l"(v));
}
static __device__ __forceinline__ unsigned long long ffma2(
    unsigned long long a, unsigned long long b, unsigned long long c) {
    unsigned long long d;
    asm("fma.rn.f32x2 %0, %1, %2, %3;" : "=l"(d) : "l"(a), "l"(b), "l"(c));
    return d;
}

static __device__ __forceinline__ bool read_mask(const void* m, int idx, int mode) {
    if (mode == 1) return ((const int*)m)[idx] != 0;
    if (mode == 2) return ((const float*)m)[idx] != 0.0f;
    return ((const unsigned char*)m)[idx] != 0;
}

// Replay-safe grid-wide barrier (grid == 148 == SM count, 1 block/SM).
static __device__ __forceinline__ void grid_barrier() {
    __syncthreads();
    if (threadIdx.x == 0) {
        unsigned gen = g_gen;
        __threadfence();
        if (atomicAdd(&g_arrive, 1u) == NBLK - 1u) {
            atomicExch(&g_arrive, 0u);
            __threadfence();
            g_gen = gen + 1u;
        } else {
            while (g_gen == gen) __nanosleep(40);
        }
        __threadfence();
    }
    __syncthreads();
}

// dynamic shared: finalize-phase selected-index list (N_ ints = 32 KB)
extern __shared__ int s_dyn[];

// ---------------- the single fused kernel ----------------
__global__ void __launch_bounds__(TPB, 1)
fused_kernel(const float* __restrict__ points, const float* __restrict__ features,
             const void* __restrict__ mask,
             const float* __restrict__ W1, const float* __restrict__ b1,
             const float* __restrict__ W2, const float* __restrict__ b2,
             const float* __restrict__ W3, const float* __restrict__ b3,
             float* __restrict__ out) {
    // weights staged as f32x2 neuron pairs, 4 neurons per ulonglong2 (LDS.128)
    __shared__ ulonglong2         sW1[NIN_ * 16];  // [j][p]: neurons 4p..4p+3
    __shared__ unsigned long long sB1[32];
    __shared__ ulonglong2         sW2[64 * 8];     // [j][q]: neurons 4q..4q+3
    __shared__ unsigned long long sB2[16];
    __shared__ float              sW3[32];
    __shared__ float              sB3v;
    __shared__ int                s_fl[2];
    // finalize / counting scratch (8 warps)
    __shared__ double sred[8], sred2[8];
    __shared__ int    wsum[8], woff[8];
    __shared__ int    s_cnt;
    __shared__ double bSs, bSs2;

    const int tid  = threadIdx.x;
    const int bid  = blockIdx.x;
    const int lane = tid & 31, wid = tid >> 5;

    // ---- inline mask dtype detection (first 64 words; 0/1 data disambiguates) ----
    if (tid < 2) s_fl[tid] = 0;
    __syncthreads();
    {
        unsigned v = ((const unsigned*)mask)[tid & 63];
        if (v > 1u) atomicOr(&s_fl[0], 1);
        if (v != 0u && v != 0x3F800000u) atomicOr(&s_fl[1], 1);
    }

    // ---- PREFETCH this thread's point data into registers (overlaps staging) ----
    const int  ppt    = bid * PPB + tid;            // point id if tid < PPB
    const bool pvalid = (tid < PPB) && (ppt < NPTS);
    const int  pt     = pvalid ? ppt : (NPTS - 1);
    float4 xf[16];
    float  px = 0.f, py = 0.f, pz = 0.f;
    if (tid < PPB) {
        const float4* fv = (const float4*)(features + (size_t)pt * F_);
#pragma unroll
        for (int c = 0; c < 16; c++) xf[c] = fv[c];
        const float* pp = points + (size_t)pt * 3;
        px = pp[0]; py = pp[1]; pz = pp[2];
    }

    // ---- weight staging (all threads) ----
    for (int idx = tid; idx < NIN_ * 16; idx += TPB) {
        int j = idx >> 4, p = idx & 15;
        ulonglong2 w;
        w.x = pack2(W1[(4 * p + 0) * NIN_ + j], W1[(4 * p + 1) * NIN_ + j]);
        w.y = pack2(W1[(4 * p + 2) * NIN_ + j], W1[(4 * p + 3) * NIN_ + j]);
        sW1[idx] = w;
    }
    for (int idx = tid; idx < 64 * 8; idx += TPB) {
        int j = idx >> 3, p = idx & 7;
        ulonglong2 w;
        w.x = pack2(W2[(4 * p + 0) * 64 + j], W2[(4 * p + 1) * 64 + j]);
        w.y = pack2(W2[(4 * p + 2) * 64 + j], W2[(4 * p + 3) * 64 + j]);
        sW2[idx] = w;
    }
    if (tid < 32) sB1[tid] = pack2(b1[2 * tid], b1[2 * tid + 1]);
    if (tid < 16) sB2[tid] = pack2(b2[2 * tid], b2[2 * tid + 1]);
    if (tid < 32) sW3[tid] = W3[tid];
    if (tid == 0) sB3v = b3[0];

    // ---- feature passthrough: flat coalesced grid-stride copy (all threads) ----
    {
        const float4* src = (const float4*)features;
        float4*       dst = (float4*)(out + F_OFF);
        const int total4 = (B_ * N_ * F_) / 4;  // 524288
        for (int i = bid * TPB + tid; i < total4; i += NBLK * TPB)
            dst[i] = src[i];
    }
    __syncthreads();
    const int mode = (!s_fl[0]) ? 1 : ((!s_fl[1]) ? 2 : 0);

    // ======== MLP: 1 thread per point, 7 full warps per block ========
    if (tid < PPB) {
        const bool m = read_mask(mask, pt, mode);
        float score = 0.0f;
        if (__any_sync(0xFFFFFFFFu, m && pvalid)) {
            unsigned long long acc[32];
#pragma unroll
            for (int p = 0; p < 32; p++) acc[p] = sB1[p];

            // layer 1 — FULLY unrolled so xf/acc stay register-resident
#pragma unroll
            for (int c = 0; c < 16; c++) {
                float xs[4] = {xf[c].x, xf[c].y, xf[c].z, xf[c].w};
#pragma unroll
                for (int u = 0; u < 4; u++) {
                    unsigned long long xx = pack2(xs[u], xs[u]);
                    const ulonglong2* wrow = &sW1[(4 * c + u) * 16];
#pragma unroll
                    for (int p = 0; p < 16; p++) {
                        ulonglong2 w = wrow[p];
                        acc[2 * p]     = ffma2(xx, w.x, acc[2 * p]);
                        acc[2 * p + 1] = ffma2(xx, w.y, acc[2 * p + 1]);
                    }
                }
            }
            {   // xyz tail (inputs 64..66)
                float ptv[3] = {px, py, pz};
#pragma unroll
                for (int u = 0; u < 3; u++) {
                    unsigned long long xx = pack2(ptv[u], ptv[u]);
                    const ulonglong2* wrow = &sW1[(64 + u) * 16];
#pragma unroll
                    for (int p = 0; p < 16; p++) {
                        ulonglong2 w = wrow[p];
                        acc[2 * p]     = ffma2(xx, w.x, acc[2 * p]);
                        acc[2 * p + 1] = ffma2(xx, w.y, acc[2 * p + 1]);
                    }
                }
            }

            // relu -> h1 (register-resident; all later indexing constant)
            float h1[64];
#pragma unroll
            for (int p = 0; p < 32; p++) {
                float lo, hi;
                unpack2(acc[p], lo, hi);
                h1[2 * p]     = fmaxf(lo, 0.0f);
                h1[2 * p + 1] = fmaxf(hi, 0.0f);
            }

            // layer 2 — FULLY unrolled (h1[j] constant-indexed => registers)
            unsigned long long acc2[16];
#pragma unroll
            for (int q = 0; q < 16; q++) acc2[q] = sB2[q];
#pragma unroll
            for (int j = 0; j < 64; j++) {
                unsigned long long hh = pack2(h1[j], h1[j]);
                const ulonglong2* wrow = &sW2[j * 8];
#pragma unroll
                for (int q = 0; q < 8; q++) {
                    ulonglong2 w = wrow[q];
                    acc2[2 * q]     = ffma2(hh, w.x, acc2[2 * q]);
                    acc2[2 * q + 1] = ffma2(hh, w.y, acc2[2 * q + 1]);
                }
            }

            // layer 3 + sigmoid
            float z = sB3v;
#pragma unroll
            for (int q = 0; q < 16; q++) {
                float lo, hi;
                unpack2(acc2[q], lo, hi);
                z += fmaxf(lo, 0.0f) * sW3[2 * q] + fmaxf(hi, 0.0f) * sW3[2 * q + 1];
            }
            score = 1.0f / (1.0f + expf(-z));
        }
        if (pvalid) out[S_OFF + pt] = m ? score : 0.0f;
    }

    // ---- pre-barrier n_leaf count: blocks 144..147 handle batch bid-144 ----
    if (bid >= NBLK - B_) {
        const int b = bid - (NBLK - B_);
        int lc = 0;
#pragma unroll
        for (int k = 0; k < 32; k++)
            lc += read_mask(mask, b * N_ + tid * 32 + k, mode) ? 1 : 0;
#pragma unroll
        for (int o = 16; o > 0; o >>= 1) lc += __shfl_down_sync(0xFFFFFFFFu, lc, o);
        if (lane == 0) wsum[wid] = lc;
        __syncthreads();
        if (tid == 0) {
            int s = 0;
#pragma unroll
            for (int w = 0; w < 8; w++) s += wsum[w];
            g_nleaf[b] = s;
        }
    }

    // ================= grid-wide barrier =================
    grid_barrier();

    if (bid >= B_) return;

    // ================= finalize: batch b = bid, 256 threads =================
    const int    b      = bid;
    float*       scores = out + S_OFF + b * N_;
    const float* pts    = points + (size_t)b * N_ * 3;
    const int n_leaf = *(volatile int*)&g_nleaf[b];

    // ---- load scores, apply n_leaf<10 zeroing, sums ----
    float sv[32];
    {
        const float4* s4 = (const float4*)scores + tid * 8;
#pragma unroll
        for (int q = 0; q < 8; q++) {
            float4 v = s4[q];
            sv[4 * q + 0] = v.x; sv[4 * q + 1] = v.y;
            sv[4 * q + 2] = v.z; sv[4 * q + 3] = v.w;
        }
    }
    const float zfac = (n_leaf < 10) ? 0.0f : 1.0f;
    double ls = 0.0, ls2 = 0.0;
#pragma unroll
    for (int k = 0; k < 32; k++) {
        float s = sv[k] * zfac;
        sv[k] = s;
        ls += s; ls2 += (double)s * (double)s;
    }
    if (n_leaf < 10) {
        float4 z4 = make_float4(0.f, 0.f, 0.f, 0.f);
        float4* s4 = (float4*)scores + tid * 8;
#pragma unroll
        for (int q = 0; q < 8; q++) s4[q] = z4;
    }
#pragma unroll
    for (int o = 16; o > 0; o >>= 1) {
        ls  += __shfl_down_sync(0xFFFFFFFFu, ls, o);
        ls2 += __shfl_down_sync(0xFFFFFFFFu, ls2, o);
    }
    if (lane == 0) { sred[wid] = ls; sred2[wid] = ls2; }
    __syncthreads();
    if (tid == 0) {
        double a = 0.0, c = 0.0;
#pragma unroll
        for (int w = 0; w < 8; w++) { a += sred[w]; c += sred2[w]; }
        bSs = a; bSs2 = c;
    }
    __syncthreads();

    // ---- selection (> 0.7), stable compaction of INDICES into shared ----
    int c = 0;
#pragma unroll
    for (int k = 0; k < 32; k++) c += (sv[k] > 0.7f) ? 1 : 0;
    int incl = c;
#pragma unroll
    for (int o = 1; o < 32; o <<= 1) {
        int t = __shfl_up_sync(0xFFFFFFFFu, incl, o);
        if (lane >= o) incl += t;
    }
    if (lane == 31) wsum[wid] = incl;
    __syncthreads();
    if (tid == 0) {
        int run = 0;
#pragma unroll
        for (int w = 0; w < 8; w++) { int t = wsum[w]; woff[w] = run; run += t; }
        s_cnt = run;
    }
    __syncthreads();
    int       pos = incl - c + woff[wid];
    const int cnt = s_cnt;
#pragma unroll
    for (int k = 0; k < 32; k++) {
        if (sv[k] > 0.7f) s_dyn[pos++] = tid * 32 + k;
    }
    __syncthreads();

    // ---- consecutive-distance variance among selected points ----
    double ld = 0.0, ld2 = 0.0;
    for (int k = tid; k < cnt - 1; k += TPB) {
        int i0 = s_dyn[k], i1 = s_dyn[k + 1];
        float dx = pts[i1 * 3 + 0] - pts[i0 * 3 + 0];
        float dy = pts[i1 * 3 + 1] - pts[i0 * 3 + 1];
        float dz = pts[i1 * 3 + 2] - pts[i0 * 3 + 2];
        float dd = sqrtf(dx * dx + dy * dy + dz * dz);
        ld += dd; ld2 += (double)dd * (double)dd;
    }
#pragma unroll
    for (int o = 16; o > 0; o >>= 1) {
        ld  += __shfl_down_sync(0xFFFFFFFFu, ld, o);
        ld2 += __shfl_down_sync(0xFFFFFFFFu, ld2, o);
    }
    if (lane == 0) { sred[wid] = ld; sred2[wid] = ld2; }
    __syncthreads();
    if (tid == 0) {
        double Sd = 0.0, Sd2 = 0.0;
#pragma unroll
        for (int w = 0; w < 8; w++) { Sd += sred[w]; Sd2 += sred2[w]; }

        const double Ss = bSs, Ss2 = bSs2;
        double nl    = (double)n_leaf;
        double meanS = Ss / fmax(nl, 1.0);
        float  clarity = (float)((Ss2 - nl * meanS * meanS) / fmax(nl - 1.0, 1.0));
        int np = cnt - 1; if (np < 0) np = 0;
        double dnp   = (double)np;
        double meanD = Sd / fmax(dnp, 1.0);
        float  dvar  = (float)((Sd2 - dnp * meanD * meanD) / fmax(dnp - 1.0, 1.0));
        float cont = 1.0f / (dvar + 1e-8f);
        cont = fminf(fmaxf(cont, 0.0f), 1.0f);
        if (!(cnt > 5)) cont = 0.0f;
        float conf = fminf(fmaxf(clarity * cont, 0.0f), 1.0f);
        if (n_leaf == 0) conf = 0.0f;
        out[C_OFF + b] = conf;
    }
}

// ---------------- launch ----------------
extern "C" void kernel_launch(void* const* d_in, const int* in_sizes, int n_in,
                              void* d_out, int out_size) {
    const float* points   = (const float*)d_in[0];
    const float* features = (const float*)d_in[1];
    const void*  mask     = d_in[2];
    const float* W1 = (const float*)d_in[3];
    const float* b1 = (const float*)d_in[4];
    const float* W2 = (const float*)d_in[5];
    const float* b2 = (const float*)d_in[6];
    const float* W3 = (const float*)d_in[7];
    const float* b3 = (const float*)d_in[8];
    float* out = (float*)d_out;

    cudaFuncSetAttribute(fused_kernel,
                         cudaFuncAttributeMaxDynamicSharedMemorySize,
                         N_ * (int)sizeof(int));
    fused_kernel<<<NBLK, TPB, N_ * sizeof(int)>>>(points, features, mask,
                                                  W1, b1, W2, b2, W3, b3, out);
}